// round 12
// baseline (speedup 1.0000x reference)
#include <cuda_runtime.h>
#include <cuda_bf16.h>
#include <math.h>
#include <stdint.h>

// Problem constants
#define BATCH 2
#define SEQ   2048
#define DMODEL 1024
#define NHEAD 16
#define DK    64
#define MROWS (BATCH*SEQ)   // 4096

// ---------------- scratch (allocation-free rule: __device__ globals) ----------
__device__ float g_Q[MROWS * DMODEL];   // (B*H, S, DK), tf32-rounded, pre-scaled 1/8
__device__ float g_K[MROWS * DMODEL];   // tf32-rounded
__device__ float g_V[MROWS * DMODEL];   // tf32-rounded
__device__ float g_A[MROWS * DMODEL];   // attention out, merged (B,S,D), tf32-rounded
// pre-rounded (tf32) copies of raw inputs
__device__ float g_rq[MROWS * DMODEL];
__device__ float g_rk[MROWS * DMODEL];
__device__ float g_rv[MROWS * DMODEL];
__device__ float g_rwq[DMODEL * DMODEL];
__device__ float g_rwk[DMODEL * DMODEL];
__device__ float g_rwv[DMODEL * DMODEL];
__device__ float g_rwo[DMODEL * DMODEL];

// =============================================================================
// helpers
// =============================================================================
__device__ __forceinline__ float to_tf32(float x) {
    float r;
    asm("cvt.rna.tf32.f32 %0, %1;" : "=f"(r) : "f"(x));
    return r;
}

__device__ __forceinline__ void mma_tf32(float* c, const uint32_t* a, const uint32_t* b) {
    asm volatile(
        "mma.sync.aligned.m16n8k8.row.col.f32.tf32.tf32.f32 "
        "{%0,%1,%2,%3}, {%4,%5,%6,%7}, {%8,%9}, {%0,%1,%2,%3};"
        : "+f"(c[0]), "+f"(c[1]), "+f"(c[2]), "+f"(c[3])
        : "r"(a[0]), "r"(a[1]), "r"(a[2]), "r"(a[3]), "r"(b[0]), "r"(b[1]));
}

// x4 ldmatrix on fp32 data (b16-pair view). Per 8x4-tf32 submatrix, lane L gets
// element [row L/4][col L%4] -> exactly the tf32 m16n8k8 fragment layouts.
__device__ __forceinline__ void ldsm4(uint32_t* r, uint32_t saddr) {
    asm volatile("ldmatrix.sync.aligned.m8n8.x4.shared.b16 {%0,%1,%2,%3}, [%4];"
                 : "=r"(r[0]), "=r"(r[1]), "=r"(r[2]), "=r"(r[3]) : "r"(saddr));
}

__device__ __forceinline__ void cp16(uint32_t dst, const void* src) {
    asm volatile("cp.async.cg.shared.global [%0], [%1], 16;" :: "r"(dst), "l"(src));
}
__device__ __forceinline__ void cp_commit() { asm volatile("cp.async.commit_group;"); }
template<int N> __device__ __forceinline__ void cp_wait() {
    asm volatile("cp.async.wait_group %0;" :: "n"(N));
}

// ---------------- batched pre-round pass: dst[i] = tf32_rna(src[i]) -----------
struct Round4 {
    const float4* src[4];
    float4*       dst[4];
};

__global__ __launch_bounds__(256) void round_batch_kernel(Round4 a, int n4)
{
    const int z = blockIdx.z;
    const float4* __restrict__ src = a.src[z];
    float4* __restrict__ dst = a.dst[z];
    int i = blockIdx.x * blockDim.x + threadIdx.x;
    if (i < n4) {
        float4 v = src[i];
        v.x = to_tf32(v.x); v.y = to_tf32(v.y);
        v.z = to_tf32(v.z); v.w = to_tf32(v.w);
        dst[i] = v;
    }
}

// =============================================================================
// tf32 GEMM: C[m,n] = sum_k A[m,k]*W[n,k] + bias[n]; inputs pre-rounded tf32.
// Block 128x128, K-tile 32, 2-stage cp.async, 8 warps (warp tile 64x32), LDSM.
// K-tile loop computes ks=0 BEFORE issuing the next-tile prefetch so the tensor
// pipe starts immediately after the barrier.
// =============================================================================
#define TBM 128
#define TBN 128
#define TBK 32
#define AST 36                 // 144B row stride: LDSM bank-phase 4r mod 32 -> conflict-free
#define GEMM_STAGE (TBM*AST)
#define NKT (DMODEL/TBK)       // 32

__device__ __forceinline__ void gemm_core(
    const float* __restrict__ A, const float* __restrict__ W,
    const float* __restrict__ bias, float* __restrict__ C,
    int split, float premul, float* As, float* Bs)
{
    const int tid  = threadIdx.x;
    const int wid  = tid >> 5;
    const int lane = tid & 31;
    const int wm   = wid & 1;
    const int wn   = wid >> 1;
    const int g    = lane >> 2;
    const int t4   = lane & 3;
    const int l15  = lane & 15;          // ldmatrix row within 16
    const int lc4  = (lane >> 4) * 4;    // ldmatrix col half (0 or 4)

    const int m0 = blockIdx.y * TBM;
    const int n0 = blockIdx.x * TBN;

    const int c4   = tid & 7;
    const int row0 = tid >> 3;

    const uint32_t as_u = (uint32_t)__cvta_generic_to_shared(As);
    const uint32_t bs_u = (uint32_t)__cvta_generic_to_shared(Bs);

    float acc[4][4][4];
#pragma unroll
    for (int mt = 0; mt < 4; mt++)
#pragma unroll
        for (int nt = 0; nt < 4; nt++)
#pragma unroll
            for (int i = 0; i < 4; i++) acc[mt][nt][i] = 0.f;

    // stage 0
#pragma unroll
    for (int rep = 0; rep < 4; rep++) {
        const int row = row0 + 32 * rep;
        cp16(as_u + (uint32_t)(row * AST + c4 * 4) * 4,
             A + (size_t)(m0 + row) * DMODEL + c4 * 4);
        cp16(bs_u + (uint32_t)(row * AST + c4 * 4) * 4,
             W + (size_t)(n0 + row) * DMODEL + c4 * 4);
    }
    cp_commit();

    for (int t = 0; t < NKT; t++) {
        cp_wait<0>();
        __syncthreads();

        const uint32_t a_su = as_u + (uint32_t)((t & 1) * GEMM_STAGE) * 4;
        const uint32_t b_su = bs_u + (uint32_t)((t & 1) * GEMM_STAGE) * 4;

        // one ks step: 6 LDSM + 16 HMMA
#define GEMM_KS(KS) do {                                                            \
            const int kk_ = (KS) * 8;                                               \
            uint32_t af_[4][4];                                                     \
            _Pragma("unroll")                                                       \
            for (int mt_ = 0; mt_ < 4; mt_++)                                       \
                ldsm4(af_[mt_],                                                     \
                      a_su + (uint32_t)((wm * 64 + mt_ * 16 + l15) * AST + kk_ + lc4) * 4); \
            uint32_t bfr_[2][4];                                                    \
            _Pragma("unroll")                                                       \
            for (int np_ = 0; np_ < 2; np_++)                                       \
                ldsm4(bfr_[np_],                                                    \
                      b_su + (uint32_t)((wn * 32 + np_ * 16 + l15) * AST + kk_ + lc4) * 4); \
            _Pragma("unroll")                                                       \
            for (int mt_ = 0; mt_ < 4; mt_++)                                       \
                _Pragma("unroll")                                                   \
                for (int nt_ = 0; nt_ < 4; nt_++) {                                 \
                    uint32_t b_[2];                                                 \
                    b_[0] = (nt_ & 1) ? bfr_[nt_ >> 1][1] : bfr_[nt_ >> 1][0];      \
                    b_[1] = (nt_ & 1) ? bfr_[nt_ >> 1][3] : bfr_[nt_ >> 1][2];      \
                    mma_tf32(acc[mt_][nt_], af_[mt_], b_);                          \
                }                                                                   \
        } while (0)

        // start the tensor pipe right away
        GEMM_KS(0);

        // then issue next-tile prefetch (latency covered by ks 1..3)
        if (t + 1 < NKT) {
            const int st = (t + 1) & 1;
            const int k0 = (t + 1) * TBK;
#pragma unroll
            for (int rep = 0; rep < 4; rep++) {
                const int row = row0 + 32 * rep;
                cp16(as_u + (uint32_t)(st * GEMM_STAGE + row * AST + c4 * 4) * 4,
                     A + (size_t)(m0 + row) * DMODEL + k0 + c4 * 4);
                cp16(bs_u + (uint32_t)(st * GEMM_STAGE + row * AST + c4 * 4) * 4,
                     W + (size_t)(n0 + row) * DMODEL + k0 + c4 * 4);
            }
            cp_commit();
        }

        GEMM_KS(1);
        GEMM_KS(2);
        GEMM_KS(3);
#undef GEMM_KS
    }

    // epilogue
#pragma unroll
    for (int mt = 0; mt < 4; mt++) {
#pragma unroll
        for (int nt = 0; nt < 4; nt++) {
            const int n = n0 + wn * 32 + nt * 8 + t4 * 2;
            const float2 bv = *(const float2*)&bias[n];
#pragma unroll
            for (int half = 0; half < 2; half++) {
                const int m = m0 + wm * 64 + mt * 16 + g + half * 8;
                float2 v;
                v.x = acc[mt][nt][half * 2 + 0] + bv.x;
                v.y = acc[mt][nt][half * 2 + 1] + bv.y;
                if (split) {
                    v.x = to_tf32(v.x * premul);
                    v.y = to_tf32(v.y * premul);
                    const int b = m >> 11, s = m & 2047;
                    const int h = n >> 6,  dk = n & 63;
                    *(float2*)&C[(((size_t)(b * NHEAD + h)) * SEQ + s) * DK + dk] = v;
                } else {
                    *(float2*)&C[(size_t)m * DMODEL + n] = v;
                }
            }
        }
    }
}

struct QKVArgs {
    const float *x[3];
    const float *W[3];
    const float *b[3];
    float *out[3];
};

#define GEMM_SMEM (2 * 2 * GEMM_STAGE * (int)sizeof(float))   // 73728

__global__ __launch_bounds__(256, 2) void qkv_gemm_kernel(QKVArgs args) {
    extern __shared__ float smg[];
    float* As = smg;
    float* Bs = smg + 2 * GEMM_STAGE;
    const int z = blockIdx.z;
    const float premul = (z == 0) ? 0.125f : 1.0f;   // fold 1/sqrt(dk) into Q
    gemm_core(args.x[z], args.W[z], args.b[z], args.out[z], 1, premul, As, Bs);
}

__global__ __launch_bounds__(256, 2) void o_gemm_kernel(
    const float* __restrict__ A, const float* __restrict__ W,
    const float* __restrict__ bias, float* __restrict__ C) {
    extern __shared__ float smg[];
    float* As = smg;
    float* Bs = smg + 2 * GEMM_STAGE;
    gemm_core(A, W, bias, C, 0, 1.0f, As, Bs);
}

// =============================================================================
// Tensor-core flash attention (causal), tf32 mma, cp.async KV pipeline, LDSM.
// Q,K,V: (B*H, S, DK), tf32-rounded (Q pre-scaled). Out: merged (B,S,D), tf32.
// Block: 128 q-rows, 8 warps; warp w owns rows w*16..+15. Key tile 64.
// =============================================================================
#define FQ 128
#define KT 64
#define KS_ST 68   // 272B stride: LDSM bank-phase 4r mod 32 -> conflict-free
#define VS_ST 72   // bank(8t4+g) conflict-free scalar pattern
#define PS_ST 68
#define KS_STAGE (KT * KS_ST)
#define VS_STAGE (KT * VS_ST)
#define FLASH_SMEM ((2*KS_STAGE + 2*VS_STAGE + FQ*PS_ST) * (int)sizeof(float)) // 106496

__global__ __launch_bounds__(256, 2) void flash_mma_kernel(
    const float* __restrict__ Q, const float* __restrict__ K,
    const float* __restrict__ V, float* __restrict__ Out)
{
    extern __shared__ float sm[];
    float* Ks = sm;
    float* Vs = Ks + 2 * KS_STAGE;
    float* Ps = Vs + 2 * VS_STAGE;

    const int qi = gridDim.x - 1 - blockIdx.x;   // longest blocks first
    const int bh = blockIdx.y;
    const int tid = threadIdx.x;
    const int w = tid >> 5, lane = tid & 31;
    const int g = lane >> 2, t4 = lane & 3;
    const int l15 = lane & 15;
    const int lc4 = (lane >> 4) * 4;

    const uint32_t ks_u = (uint32_t)__cvta_generic_to_shared(Ks);
    const uint32_t vs_u = (uint32_t)__cvta_generic_to_shared(Vs);
    const uint32_t ps_u = (uint32_t)__cvta_generic_to_shared(Ps);

    const float* Qg = Q + ((size_t)bh * SEQ + qi * FQ) * DK;
    const float* Kg = K + (size_t)bh * SEQ * DK;
    const float* Vg = V + (size_t)bh * SEQ * DK;

#pragma unroll
    for (int i = 0; i < 8; i++) {
        int lin = tid + i * 256;
        int row = lin >> 4, c4 = lin & 15;
        cp16(ps_u + (uint32_t)(row * PS_ST + c4 * 4) * 4, Qg + row * DK + c4 * 4);
    }
    cp_commit();

#pragma unroll
    for (int i = 0; i < 4; i++) {
        int lin = tid + i * 256;
        int row = lin >> 4, c4 = lin & 15;
        cp16(ks_u + (uint32_t)(row * KS_ST + c4 * 4) * 4, Kg + row * DK + c4 * 4);
        cp16(vs_u + (uint32_t)(row * VS_ST + c4 * 4) * 4, Vg + row * DK + c4 * 4);
    }
    cp_commit();

    cp_wait<1>();
    __syncthreads();

    uint32_t qa[8][4];
#pragma unroll
    for (int kt = 0; kt < 8; kt++)
        ldsm4(qa[kt], ps_u + (uint32_t)((w * 16 + l15) * PS_ST + kt * 8 + lc4) * 4);

    float m0 = -1e30f, m1 = -1e30f, l0 = 0.f, l1 = 0.f;
    float oacc[8][4];
#pragma unroll
    for (int nt = 0; nt < 8; nt++)
#pragma unroll
        for (int i = 0; i < 4; i++) oacc[nt][i] = 0.f;

    const int njb = 2 * qi + 2;
    const int row0 = qi * FQ + w * 16 + g;
    const int row1 = row0 + 8;

    for (int jb = 0; jb < njb; jb++) {
        cp_wait<0>();
        __syncthreads();

        if (jb + 1 < njb) {
            const int st = (jb + 1) & 1;
            const float* Kn = Kg + (size_t)(jb + 1) * KT * DK;
            const float* Vn = Vg + (size_t)(jb + 1) * KT * DK;
#pragma unroll
            for (int i = 0; i < 4; i++) {
                int lin = tid + i * 256;
                int row = lin >> 4, c4 = lin & 15;
                cp16(ks_u + (uint32_t)(st * KS_STAGE + row * KS_ST + c4 * 4) * 4,
                     Kn + row * DK + c4 * 4);
                cp16(vs_u + (uint32_t)(st * VS_STAGE + row * VS_ST + c4 * 4) * 4,
                     Vn + row * DK + c4 * 4);
            }
            cp_commit();
        }

        const uint32_t k_su = ks_u + (uint32_t)((jb & 1) * KS_STAGE) * 4;
        const float* v_s = Vs + (jb & 1) * VS_STAGE;

        float sacc[8][4];
#pragma unroll
        for (int nt = 0; nt < 8; nt++)
#pragma unroll
            for (int i = 0; i < 4; i++) sacc[nt][i] = 0.f;

#pragma unroll
        for (int kt = 0; kt < 8; kt++) {
            uint32_t kfr[4][4];
#pragma unroll
            for (int np = 0; np < 4; np++)
                ldsm4(kfr[np], k_su + (uint32_t)((np * 16 + l15) * KS_ST + kt * 8 + lc4) * 4);
#pragma unroll
            for (int nt = 0; nt < 8; nt++) {
                uint32_t b[2];
                b[0] = (nt & 1) ? kfr[nt >> 1][1] : kfr[nt >> 1][0];
                b[1] = (nt & 1) ? kfr[nt >> 1][3] : kfr[nt >> 1][2];
                mma_tf32(sacc[nt], qa[kt], b);
            }
        }

        if (jb >= 2 * qi) {
#pragma unroll
            for (int nt = 0; nt < 8; nt++) {
                int key = jb * KT + nt * 8 + 2 * t4;
                if (key     > row0) sacc[nt][0] = -1e30f;
                if (key + 1 > row0) sacc[nt][1] = -1e30f;
                if (key     > row1) sacc[nt][2] = -1e30f;
                if (key + 1 > row1) sacc[nt][3] = -1e30f;
            }
        }

        float mx0 = -1e30f, mx1 = -1e30f;
#pragma unroll
        for (int nt = 0; nt < 8; nt++) {
            mx0 = fmaxf(mx0, fmaxf(sacc[nt][0], sacc[nt][1]));
            mx1 = fmaxf(mx1, fmaxf(sacc[nt][2], sacc[nt][3]));
        }
        mx0 = fmaxf(mx0, __shfl_xor_sync(0xffffffffu, mx0, 1));
        mx0 = fmaxf(mx0, __shfl_xor_sync(0xffffffffu, mx0, 2));
        mx1 = fmaxf(mx1, __shfl_xor_sync(0xffffffffu, mx1, 1));
        mx1 = fmaxf(mx1, __shfl_xor_sync(0xffffffffu, mx1, 2));
        const float mn0 = fmaxf(m0, mx0);
        const float mn1 = fmaxf(m1, mx1);

        float sum0 = 0.f, sum1 = 0.f;
#pragma unroll
        for (int nt = 0; nt < 8; nt++) {
            float p00 = to_tf32(__expf(sacc[nt][0] - mn0));
            float p01 = to_tf32(__expf(sacc[nt][1] - mn0));
            float p10 = to_tf32(__expf(sacc[nt][2] - mn1));
            float p11 = to_tf32(__expf(sacc[nt][3] - mn1));
            sum0 += p00 + p01;
            sum1 += p10 + p11;
            sacc[nt][0] = p00; sacc[nt][1] = p01;
            sacc[nt][2] = p10; sacc[nt][3] = p11;
        }
        sum0 += __shfl_xor_sync(0xffffffffu, sum0, 1);
        sum0 += __shfl_xor_sync(0xffffffffu, sum0, 2);
        sum1 += __shfl_xor_sync(0xffffffffu, sum1, 1);
        sum1 += __shfl_xor_sync(0xffffffffu, sum1, 2);

        const float a0 = __expf(m0 - mn0);
        const float a1 = __expf(m1 - mn1);
        l0 = l0 * a0 + sum0;
        l1 = l1 * a1 + sum1;
        m0 = mn0; m1 = mn1;
#pragma unroll
        for (int nt = 0; nt < 8; nt++) {
            oacc[nt][0] *= a0; oacc[nt][1] *= a0;
            oacc[nt][2] *= a1; oacc[nt][3] *= a1;
        }

        __syncwarp();
        float* prow0 = &Ps[(w * 16 + g) * PS_ST];
        float* prow1 = &Ps[(w * 16 + g + 8) * PS_ST];
#pragma unroll
        for (int nt = 0; nt < 8; nt++) {
            *(float2*)&prow0[nt * 8 + 2 * t4] = make_float2(sacc[nt][0], sacc[nt][1]);
            *(float2*)&prow1[nt * 8 + 2 * t4] = make_float2(sacc[nt][2], sacc[nt][3]);
        }
        __syncwarp();

#pragma unroll
        for (int kt = 0; kt < 8; kt++) {
            uint32_t pa[4];
            ldsm4(pa, ps_u + (uint32_t)((w * 16 + l15) * PS_ST + kt * 8 + lc4) * 4);
#pragma unroll
            for (int nt = 0; nt < 8; nt++) {
                uint32_t vb[2];
                vb[0] = __float_as_uint(v_s[(kt * 8 + t4    ) * VS_ST + nt * 8 + g]);
                vb[1] = __float_as_uint(v_s[(kt * 8 + t4 + 4) * VS_ST + nt * 8 + g]);
                mma_tf32(oacc[nt], pa, vb);
            }
        }
    }

    const float i0 = 1.f / l0, i1 = 1.f / l1;
    const int b = bh >> 4, h = bh & 15;
#pragma unroll
    for (int nt = 0; nt < 8; nt++) {
        const int col = h * DK + nt * 8 + 2 * t4;
        float2 v0 = make_float2(to_tf32(oacc[nt][0] * i0), to_tf32(oacc[nt][1] * i0));
        float2 v1 = make_float2(to_tf32(oacc[nt][2] * i1), to_tf32(oacc[nt][3] * i1));
        *(float2*)&Out[((size_t)(b * SEQ + row0)) * DMODEL + col] = v0;
        *(float2*)&Out[((size_t)(b * SEQ + row1)) * DMODEL + col] = v1;
    }
}

// ---------------- launch ------------------------------------------------------
extern "C" void kernel_launch(void* const* d_in, const int* in_sizes, int n_in,
                              void* d_out, int out_size)
{
    const float* query = (const float*)d_in[0];
    const float* key   = (const float*)d_in[1];
    const float* value = (const float*)d_in[2];
    // d_in[3] = mask (causal triu, fixed by problem definition) -> analytic
    const float* Wq = (const float*)d_in[4];
    const float* bq = (const float*)d_in[5];
    const float* Wk = (const float*)d_in[6];
    const float* bk = (const float*)d_in[7];
    const float* Wv = (const float*)d_in[8];
    const float* bv = (const float*)d_in[9];
    const float* Wo = (const float*)d_in[10];
    const float* bo = (const float*)d_in[11];
    float* out = (float*)d_out;

    float *pQ, *pK, *pV, *pA;
    float *prq, *prk, *prv, *prwq, *prwk, *prwv, *prwo;
    cudaGetSymbolAddress((void**)&pQ, g_Q);
    cudaGetSymbolAddress((void**)&pK, g_K);
    cudaGetSymbolAddress((void**)&pV, g_V);
    cudaGetSymbolAddress((void**)&pA, g_A);
    cudaGetSymbolAddress((void**)&prq, g_rq);
    cudaGetSymbolAddress((void**)&prk, g_rk);
    cudaGetSymbolAddress((void**)&prv, g_rv);
    cudaGetSymbolAddress((void**)&prwq, g_rwq);
    cudaGetSymbolAddress((void**)&prwk, g_rwk);
    cudaGetSymbolAddress((void**)&prwv, g_rwv);
    cudaGetSymbolAddress((void**)&prwo, g_rwo);

    cudaFuncSetAttribute(qkv_gemm_kernel,
                         cudaFuncAttributeMaxDynamicSharedMemorySize, GEMM_SMEM);
    cudaFuncSetAttribute(o_gemm_kernel,
                         cudaFuncAttributeMaxDynamicSharedMemorySize, GEMM_SMEM);
    cudaFuncSetAttribute(flash_mma_kernel,
                         cudaFuncAttributeMaxDynamicSharedMemorySize, FLASH_SMEM);

    // pre-round all GEMM inputs to tf32 (RNA): 2 batched launches
    const int NX4 = MROWS * DMODEL / 4;     // 1M float4 per activation tensor
    const int NW4 = DMODEL * DMODEL / 4;    // 256K float4 per weight tensor

    Round4 ra;
    ra.src[0] = (const float4*)query; ra.dst[0] = (float4*)prq;
    ra.src[1] = (const float4*)key;   ra.dst[1] = (float4*)prk;
    ra.src[2] = (const float4*)value; ra.dst[2] = (float4*)prv;
    ra.src[3] = (const float4*)query; ra.dst[3] = (float4*)prq;  // unused slot
    round_batch_kernel<<<dim3(NX4 / 256, 1, 3), 256>>>(ra, NX4);

    Round4 rw;
    rw.src[0] = (const float4*)Wq; rw.dst[0] = (float4*)prwq;
    rw.src[1] = (const float4*)Wk; rw.dst[1] = (float4*)prwk;
    rw.src[2] = (const float4*)Wv; rw.dst[2] = (float4*)prwv;
    rw.src[3] = (const float4*)Wo; rw.dst[3] = (float4*)prwo;
    round_batch_kernel<<<dim3(NW4 / 256, 1, 4), 256>>>(rw, NW4);

    QKVArgs args;
    args.x[0] = prq;  args.x[1] = prk;  args.x[2] = prv;
    args.W[0] = prwq; args.W[1] = prwk; args.W[2] = prwv;
    args.b[0] = bq;   args.b[1] = bk;   args.b[2] = bv;
    args.out[0] = pQ; args.out[1] = pK; args.out[2] = pV;

    qkv_gemm_kernel<<<dim3(DMODEL / TBN, MROWS / TBM, 3), 256, GEMM_SMEM>>>(args);

    flash_mma_kernel<<<dim3(SEQ / FQ, BATCH * NHEAD), 256, FLASH_SMEM>>>(pQ, pK, pV, pA);

    o_gemm_kernel<<<dim3(DMODEL / TBN, MROWS / TBM), 256, GEMM_SMEM>>>(pA, prwo, bo, out);
}

// round 17
// speedup vs baseline: 1.5391x; 1.5391x over previous
#include <cuda_runtime.h>
#include <cuda_bf16.h>
#include <math.h>
#include <stdint.h>

// Problem constants
#define BATCH 2
#define SEQ   2048
#define DMODEL 1024
#define NHEAD 16
#define DK    64
#define MROWS (BATCH*SEQ)   // 4096

// ---------------- scratch (allocation-free rule: __device__ globals) ----------
__device__ float g_Q[MROWS * DMODEL];   // (B*H, S, DK), tf32-rounded, pre-scaled 1/8
__device__ float g_K[MROWS * DMODEL];   // tf32-rounded
__device__ float g_V[MROWS * DMODEL];   // tf32-rounded
__device__ float g_A[MROWS * DMODEL];   // attention out, merged (B,S,D), tf32-rounded
// pre-rounded (tf32) copies of raw inputs
__device__ float g_rq[MROWS * DMODEL];
__device__ float g_rk[MROWS * DMODEL];
__device__ float g_rv[MROWS * DMODEL];
__device__ float g_rwq[DMODEL * DMODEL];
__device__ float g_rwk[DMODEL * DMODEL];
__device__ float g_rwv[DMODEL * DMODEL];
__device__ float g_rwo[DMODEL * DMODEL];

// =============================================================================
// helpers
// =============================================================================
__device__ __forceinline__ float to_tf32(float x) {
    float r;
    asm("cvt.rna.tf32.f32 %0, %1;" : "=f"(r) : "f"(x));
    return r;
}

__device__ __forceinline__ void mma_tf32(float* c, const uint32_t* a, const uint32_t* b) {
    asm volatile(
        "mma.sync.aligned.m16n8k8.row.col.f32.tf32.tf32.f32 "
        "{%0,%1,%2,%3}, {%4,%5,%6,%7}, {%8,%9}, {%0,%1,%2,%3};"
        : "+f"(c[0]), "+f"(c[1]), "+f"(c[2]), "+f"(c[3])
        : "r"(a[0]), "r"(a[1]), "r"(a[2]), "r"(a[3]), "r"(b[0]), "r"(b[1]));
}

// x4 ldmatrix on fp32 data (b16-pair view). Per 8x4-tf32 submatrix, lane L gets
// element [row L/4][col L%4] -> exactly the tf32 m16n8k8 fragment layouts.
__device__ __forceinline__ void ldsm4(uint32_t* r, uint32_t saddr) {
    asm volatile("ldmatrix.sync.aligned.m8n8.x4.shared.b16 {%0,%1,%2,%3}, [%4];"
                 : "=r"(r[0]), "=r"(r[1]), "=r"(r[2]), "=r"(r[3]) : "r"(saddr));
}

__device__ __forceinline__ void cp16(uint32_t dst, const void* src) {
    asm volatile("cp.async.cg.shared.global [%0], [%1], 16;" :: "r"(dst), "l"(src));
}
__device__ __forceinline__ void cp_commit() { asm volatile("cp.async.commit_group;"); }
template<int N> __device__ __forceinline__ void cp_wait() {
    asm volatile("cp.async.wait_group %0;" :: "n"(N));
}

// ---------------- batched pre-round pass: dst[i] = tf32_rna(src[i]) -----------
struct Round4 {
    const float4* src[4];
    float4*       dst[4];
};

__global__ __launch_bounds__(256) void round_batch_kernel(Round4 a, int n4)
{
    const int z = blockIdx.z;
    const float4* __restrict__ src = a.src[z];
    float4* __restrict__ dst = a.dst[z];
    int i = blockIdx.x * blockDim.x + threadIdx.x;
    if (i < n4) {
        float4 v = src[i];
        v.x = to_tf32(v.x); v.y = to_tf32(v.y);
        v.z = to_tf32(v.z); v.w = to_tf32(v.w);
        dst[i] = v;
    }
}

// =============================================================================
// tf32 GEMM: C[m,n] = sum_k A[m,k]*W[n,k] + bias[n]; inputs pre-rounded tf32.
// Block 128x128, K-tile 32, 2-stage cp.async, 8 warps (warp tile 64x32), LDSM.
// (exact R8 structure: prefetch issued at top of K-tile loop)
// =============================================================================
#define TBM 128
#define TBN 128
#define TBK 32
#define AST 36                 // 144B row stride: LDSM bank-phase 4r mod 32 -> conflict-free
#define GEMM_STAGE (TBM*AST)
#define NKT (DMODEL/TBK)       // 32

__device__ __forceinline__ void gemm_core(
    const float* __restrict__ A, const float* __restrict__ W,
    const float* __restrict__ bias, float* __restrict__ C,
    int split, float premul, float* As, float* Bs)
{
    const int tid  = threadIdx.x;
    const int wid  = tid >> 5;
    const int lane = tid & 31;
    const int wm   = wid & 1;
    const int wn   = wid >> 1;
    const int g    = lane >> 2;
    const int t4   = lane & 3;
    const int l15  = lane & 15;          // ldmatrix row within 16
    const int lc4  = (lane >> 4) * 4;    // ldmatrix col half (0 or 4)

    const int m0 = blockIdx.y * TBM;
    const int n0 = blockIdx.x * TBN;

    const int c4   = tid & 7;
    const int row0 = tid >> 3;

    const uint32_t as_u = (uint32_t)__cvta_generic_to_shared(As);
    const uint32_t bs_u = (uint32_t)__cvta_generic_to_shared(Bs);

    float acc[4][4][4];
#pragma unroll
    for (int mt = 0; mt < 4; mt++)
#pragma unroll
        for (int nt = 0; nt < 4; nt++)
#pragma unroll
            for (int i = 0; i < 4; i++) acc[mt][nt][i] = 0.f;

    // stage 0
#pragma unroll
    for (int rep = 0; rep < 4; rep++) {
        const int row = row0 + 32 * rep;
        cp16(as_u + (uint32_t)(row * AST + c4 * 4) * 4,
             A + (size_t)(m0 + row) * DMODEL + c4 * 4);
        cp16(bs_u + (uint32_t)(row * AST + c4 * 4) * 4,
             W + (size_t)(n0 + row) * DMODEL + c4 * 4);
    }
    cp_commit();

    for (int t = 0; t < NKT; t++) {
        cp_wait<0>();
        __syncthreads();

        if (t + 1 < NKT) {
            const int st = (t + 1) & 1;
            const int k0 = (t + 1) * TBK;
#pragma unroll
            for (int rep = 0; rep < 4; rep++) {
                const int row = row0 + 32 * rep;
                cp16(as_u + (uint32_t)(st * GEMM_STAGE + row * AST + c4 * 4) * 4,
                     A + (size_t)(m0 + row) * DMODEL + k0 + c4 * 4);
                cp16(bs_u + (uint32_t)(st * GEMM_STAGE + row * AST + c4 * 4) * 4,
                     W + (size_t)(n0 + row) * DMODEL + k0 + c4 * 4);
            }
            cp_commit();
        }

        const uint32_t a_su = as_u + (uint32_t)((t & 1) * GEMM_STAGE) * 4;
        const uint32_t b_su = bs_u + (uint32_t)((t & 1) * GEMM_STAGE) * 4;

#pragma unroll
        for (int ks = 0; ks < 4; ks++) {
            const int kk = ks * 8;
            uint32_t af[4][4];
#pragma unroll
            for (int mt = 0; mt < 4; mt++)
                ldsm4(af[mt], a_su + (uint32_t)((wm * 64 + mt * 16 + l15) * AST + kk + lc4) * 4);
            uint32_t bfr[2][4];
#pragma unroll
            for (int np = 0; np < 2; np++)
                ldsm4(bfr[np], b_su + (uint32_t)((wn * 32 + np * 16 + l15) * AST + kk + lc4) * 4);
#pragma unroll
            for (int mt = 0; mt < 4; mt++)
#pragma unroll
                for (int nt = 0; nt < 4; nt++) {
                    uint32_t b[2];
                    b[0] = (nt & 1) ? bfr[nt >> 1][1] : bfr[nt >> 1][0];
                    b[1] = (nt & 1) ? bfr[nt >> 1][3] : bfr[nt >> 1][2];
                    mma_tf32(acc[mt][nt], af[mt], b);
                }
        }
    }

    // epilogue
#pragma unroll
    for (int mt = 0; mt < 4; mt++) {
#pragma unroll
        for (int nt = 0; nt < 4; nt++) {
            const int n = n0 + wn * 32 + nt * 8 + t4 * 2;
            const float2 bv = *(const float2*)&bias[n];
#pragma unroll
            for (int half = 0; half < 2; half++) {
                const int m = m0 + wm * 64 + mt * 16 + g + half * 8;
                float2 v;
                v.x = acc[mt][nt][half * 2 + 0] + bv.x;
                v.y = acc[mt][nt][half * 2 + 1] + bv.y;
                if (split) {
                    v.x = to_tf32(v.x * premul);
                    v.y = to_tf32(v.y * premul);
                    const int b = m >> 11, s = m & 2047;
                    const int h = n >> 6,  dk = n & 63;
                    *(float2*)&C[(((size_t)(b * NHEAD + h)) * SEQ + s) * DK + dk] = v;
                } else {
                    *(float2*)&C[(size_t)m * DMODEL + n] = v;
                }
            }
        }
    }
}

struct QKVArgs {
    const float *x[3];
    const float *W[3];
    const float *b[3];
    float *out[3];
};

#define GEMM_SMEM (2 * 2 * GEMM_STAGE * (int)sizeof(float))   // 73728

__global__ __launch_bounds__(256, 2) void qkv_gemm_kernel(QKVArgs args) {
    extern __shared__ float smg[];
    float* As = smg;
    float* Bs = smg + 2 * GEMM_STAGE;
    const int z = blockIdx.z;
    const float premul = (z == 0) ? 0.125f : 1.0f;   // fold 1/sqrt(dk) into Q
    gemm_core(args.x[z], args.W[z], args.b[z], args.out[z], 1, premul, As, Bs);
}

__global__ __launch_bounds__(256, 2) void o_gemm_kernel(
    const float* __restrict__ A, const float* __restrict__ W,
    const float* __restrict__ bias, float* __restrict__ C) {
    extern __shared__ float smg[];
    float* As = smg;
    float* Bs = smg + 2 * GEMM_STAGE;
    gemm_core(A, W, bias, C, 0, 1.0f, As, Bs);
}

// =============================================================================
// Tensor-core flash attention (causal), tf32 mma, cp.async KV pipeline, LDSM.
// (byte-identical to the R8 passing version)
// =============================================================================
#define FQ 128
#define KT 64
#define KS_ST 68   // 272B stride: LDSM bank-phase 4r mod 32 -> conflict-free
#define VS_ST 72   // bank(8t4+g) conflict-free scalar pattern
#define PS_ST 68
#define KS_STAGE (KT * KS_ST)
#define VS_STAGE (KT * VS_ST)
#define FLASH_SMEM ((2*KS_STAGE + 2*VS_STAGE + FQ*PS_ST) * (int)sizeof(float)) // 106496

__global__ __launch_bounds__(256, 2) void flash_mma_kernel(
    const float* __restrict__ Q, const float* __restrict__ K,
    const float* __restrict__ V, float* __restrict__ Out)
{
    extern __shared__ float sm[];
    float* Ks = sm;
    float* Vs = Ks + 2 * KS_STAGE;
    float* Ps = Vs + 2 * VS_STAGE;

    const int qi = gridDim.x - 1 - blockIdx.x;   // longest blocks first
    const int bh = blockIdx.y;
    const int tid = threadIdx.x;
    const int w = tid >> 5, lane = tid & 31;
    const int g = lane >> 2, t4 = lane & 3;
    const int l15 = lane & 15;
    const int lc4 = (lane >> 4) * 4;

    const uint32_t ks_u = (uint32_t)__cvta_generic_to_shared(Ks);
    const uint32_t vs_u = (uint32_t)__cvta_generic_to_shared(Vs);
    const uint32_t ps_u = (uint32_t)__cvta_generic_to_shared(Ps);

    const float* Qg = Q + ((size_t)bh * SEQ + qi * FQ) * DK;
    const float* Kg = K + (size_t)bh * SEQ * DK;
    const float* Vg = V + (size_t)bh * SEQ * DK;

#pragma unroll
    for (int i = 0; i < 8; i++) {
        int lin = tid + i * 256;
        int row = lin >> 4, c4 = lin & 15;
        cp16(ps_u + (uint32_t)(row * PS_ST + c4 * 4) * 4, Qg + row * DK + c4 * 4);
    }
    cp_commit();

#pragma unroll
    for (int i = 0; i < 4; i++) {
        int lin = tid + i * 256;
        int row = lin >> 4, c4 = lin & 15;
        cp16(ks_u + (uint32_t)(row * KS_ST + c4 * 4) * 4, Kg + row * DK + c4 * 4);
        cp16(vs_u + (uint32_t)(row * VS_ST + c4 * 4) * 4, Vg + row * DK + c4 * 4);
    }
    cp_commit();

    cp_wait<1>();
    __syncthreads();

    uint32_t qa[8][4];
#pragma unroll
    for (int kt = 0; kt < 8; kt++)
        ldsm4(qa[kt], ps_u + (uint32_t)((w * 16 + l15) * PS_ST + kt * 8 + lc4) * 4);

    float m0 = -1e30f, m1 = -1e30f, l0 = 0.f, l1 = 0.f;
    float oacc[8][4];
#pragma unroll
    for (int nt = 0; nt < 8; nt++)
#pragma unroll
        for (int i = 0; i < 4; i++) oacc[nt][i] = 0.f;

    const int njb = 2 * qi + 2;
    const int row0 = qi * FQ + w * 16 + g;
    const int row1 = row0 + 8;

    for (int jb = 0; jb < njb; jb++) {
        cp_wait<0>();
        __syncthreads();

        if (jb + 1 < njb) {
            const int st = (jb + 1) & 1;
            const float* Kn = Kg + (size_t)(jb + 1) * KT * DK;
            const float* Vn = Vg + (size_t)(jb + 1) * KT * DK;
#pragma unroll
            for (int i = 0; i < 4; i++) {
                int lin = tid + i * 256;
                int row = lin >> 4, c4 = lin & 15;
                cp16(ks_u + (uint32_t)(st * KS_STAGE + row * KS_ST + c4 * 4) * 4,
                     Kn + row * DK + c4 * 4);
                cp16(vs_u + (uint32_t)(st * VS_STAGE + row * VS_ST + c4 * 4) * 4,
                     Vn + row * DK + c4 * 4);
            }
            cp_commit();
        }

        const uint32_t k_su = ks_u + (uint32_t)((jb & 1) * KS_STAGE) * 4;
        const float* v_s = Vs + (jb & 1) * VS_STAGE;

        float sacc[8][4];
#pragma unroll
        for (int nt = 0; nt < 8; nt++)
#pragma unroll
            for (int i = 0; i < 4; i++) sacc[nt][i] = 0.f;

#pragma unroll
        for (int kt = 0; kt < 8; kt++) {
            uint32_t kfr[4][4];
#pragma unroll
            for (int np = 0; np < 4; np++)
                ldsm4(kfr[np], k_su + (uint32_t)((np * 16 + l15) * KS_ST + kt * 8 + lc4) * 4);
#pragma unroll
            for (int nt = 0; nt < 8; nt++) {
                uint32_t b[2];
                b[0] = (nt & 1) ? kfr[nt >> 1][1] : kfr[nt >> 1][0];
                b[1] = (nt & 1) ? kfr[nt >> 1][3] : kfr[nt >> 1][2];
                mma_tf32(sacc[nt], qa[kt], b);
            }
        }

        if (jb >= 2 * qi) {
#pragma unroll
            for (int nt = 0; nt < 8; nt++) {
                int key = jb * KT + nt * 8 + 2 * t4;
                if (key     > row0) sacc[nt][0] = -1e30f;
                if (key + 1 > row0) sacc[nt][1] = -1e30f;
                if (key     > row1) sacc[nt][2] = -1e30f;
                if (key + 1 > row1) sacc[nt][3] = -1e30f;
            }
        }

        float mx0 = -1e30f, mx1 = -1e30f;
#pragma unroll
        for (int nt = 0; nt < 8; nt++) {
            mx0 = fmaxf(mx0, fmaxf(sacc[nt][0], sacc[nt][1]));
            mx1 = fmaxf(mx1, fmaxf(sacc[nt][2], sacc[nt][3]));
        }
        mx0 = fmaxf(mx0, __shfl_xor_sync(0xffffffffu, mx0, 1));
        mx0 = fmaxf(mx0, __shfl_xor_sync(0xffffffffu, mx0, 2));
        mx1 = fmaxf(mx1, __shfl_xor_sync(0xffffffffu, mx1, 1));
        mx1 = fmaxf(mx1, __shfl_xor_sync(0xffffffffu, mx1, 2));
        const float mn0 = fmaxf(m0, mx0);
        const float mn1 = fmaxf(m1, mx1);

        float sum0 = 0.f, sum1 = 0.f;
#pragma unroll
        for (int nt = 0; nt < 8; nt++) {
            float p00 = to_tf32(__expf(sacc[nt][0] - mn0));
            float p01 = to_tf32(__expf(sacc[nt][1] - mn0));
            float p10 = to_tf32(__expf(sacc[nt][2] - mn1));
            float p11 = to_tf32(__expf(sacc[nt][3] - mn1));
            sum0 += p00 + p01;
            sum1 += p10 + p11;
            sacc[nt][0] = p00; sacc[nt][1] = p01;
            sacc[nt][2] = p10; sacc[nt][3] = p11;
        }
        sum0 += __shfl_xor_sync(0xffffffffu, sum0, 1);
        sum0 += __shfl_xor_sync(0xffffffffu, sum0, 2);
        sum1 += __shfl_xor_sync(0xffffffffu, sum1, 1);
        sum1 += __shfl_xor_sync(0xffffffffu, sum1, 2);

        const float a0 = __expf(m0 - mn0);
        const float a1 = __expf(m1 - mn1);
        l0 = l0 * a0 + sum0;
        l1 = l1 * a1 + sum1;
        m0 = mn0; m1 = mn1;
#pragma unroll
        for (int nt = 0; nt < 8; nt++) {
            oacc[nt][0] *= a0; oacc[nt][1] *= a0;
            oacc[nt][2] *= a1; oacc[nt][3] *= a1;
        }

        __syncwarp();
        float* prow0 = &Ps[(w * 16 + g) * PS_ST];
        float* prow1 = &Ps[(w * 16 + g + 8) * PS_ST];
#pragma unroll
        for (int nt = 0; nt < 8; nt++) {
            *(float2*)&prow0[nt * 8 + 2 * t4] = make_float2(sacc[nt][0], sacc[nt][1]);
            *(float2*)&prow1[nt * 8 + 2 * t4] = make_float2(sacc[nt][2], sacc[nt][3]);
        }
        __syncwarp();

#pragma unroll
        for (int kt = 0; kt < 8; kt++) {
            uint32_t pa[4];
            ldsm4(pa, ps_u + (uint32_t)((w * 16 + l15) * PS_ST + kt * 8 + lc4) * 4);
#pragma unroll
            for (int nt = 0; nt < 8; nt++) {
                uint32_t vb[2];
                vb[0] = __float_as_uint(v_s[(kt * 8 + t4    ) * VS_ST + nt * 8 + g]);
                vb[1] = __float_as_uint(v_s[(kt * 8 + t4 + 4) * VS_ST + nt * 8 + g]);
                mma_tf32(oacc[nt], pa, vb);
            }
        }
    }

    const float i0 = 1.f / l0, i1 = 1.f / l1;
    const int b = bh >> 4, h = bh & 15;
#pragma unroll
    for (int nt = 0; nt < 8; nt++) {
        const int col = h * DK + nt * 8 + 2 * t4;
        float2 v0 = make_float2(to_tf32(oacc[nt][0] * i0), to_tf32(oacc[nt][1] * i0));
        float2 v1 = make_float2(to_tf32(oacc[nt][2] * i1), to_tf32(oacc[nt][3] * i1));
        *(float2*)&Out[((size_t)(b * SEQ + row0)) * DMODEL + col] = v0;
        *(float2*)&Out[((size_t)(b * SEQ + row1)) * DMODEL + col] = v1;
    }
}

// ---------------- launch ------------------------------------------------------
extern "C" void kernel_launch(void* const* d_in, const int* in_sizes, int n_in,
                              void* d_out, int out_size)
{
    const float* query = (const float*)d_in[0];
    const float* key   = (const float*)d_in[1];
    const float* value = (const float*)d_in[2];
    // d_in[3] = mask (causal triu, fixed by problem definition) -> analytic
    const float* Wq = (const float*)d_in[4];
    const float* bq = (const float*)d_in[5];
    const float* Wk = (const float*)d_in[6];
    const float* bk = (const float*)d_in[7];
    const float* Wv = (const float*)d_in[8];
    const float* bv = (const float*)d_in[9];
    const float* Wo = (const float*)d_in[10];
    const float* bo = (const float*)d_in[11];
    float* out = (float*)d_out;

    float *pQ, *pK, *pV, *pA;
    float *prq, *prk, *prv, *prwq, *prwk, *prwv, *prwo;
    cudaGetSymbolAddress((void**)&pQ, g_Q);
    cudaGetSymbolAddress((void**)&pK, g_K);
    cudaGetSymbolAddress((void**)&pV, g_V);
    cudaGetSymbolAddress((void**)&pA, g_A);
    cudaGetSymbolAddress((void**)&prq, g_rq);
    cudaGetSymbolAddress((void**)&prk, g_rk);
    cudaGetSymbolAddress((void**)&prv, g_rv);
    cudaGetSymbolAddress((void**)&prwq, g_rwq);
    cudaGetSymbolAddress((void**)&prwk, g_rwk);
    cudaGetSymbolAddress((void**)&prwv, g_rwv);
    cudaGetSymbolAddress((void**)&prwo, g_rwo);

    cudaFuncSetAttribute(qkv_gemm_kernel,
                         cudaFuncAttributeMaxDynamicSharedMemorySize, GEMM_SMEM);
    cudaFuncSetAttribute(o_gemm_kernel,
                         cudaFuncAttributeMaxDynamicSharedMemorySize, GEMM_SMEM);
    cudaFuncSetAttribute(flash_mma_kernel,
                         cudaFuncAttributeMaxDynamicSharedMemorySize, FLASH_SMEM);

    // pre-round all GEMM inputs to tf32 (RNA): 2 batched launches
    const int NX4 = MROWS * DMODEL / 4;     // 1M float4 per activation tensor
    const int NW4 = DMODEL * DMODEL / 4;    // 256K float4 per weight tensor

    Round4 ra;
    ra.src[0] = (const float4*)query; ra.dst[0] = (float4*)prq;
    ra.src[1] = (const float4*)key;   ra.dst[1] = (float4*)prk;
    ra.src[2] = (const float4*)value; ra.dst[2] = (float4*)prv;
    ra.src[3] = (const float4*)query; ra.dst[3] = (float4*)prq;  // unused slot
    round_batch_kernel<<<dim3(NX4 / 256, 1, 3), 256>>>(ra, NX4);

    Round4 rw;
    rw.src[0] = (const float4*)Wq; rw.dst[0] = (float4*)prwq;
    rw.src[1] = (const float4*)Wk; rw.dst[1] = (float4*)prwk;
    rw.src[2] = (const float4*)Wv; rw.dst[2] = (float4*)prwv;
    rw.src[3] = (const float4*)Wo; rw.dst[3] = (float4*)prwo;
    round_batch_kernel<<<dim3(NW4 / 256, 1, 4), 256>>>(rw, NW4);

    QKVArgs args;
    args.x[0] = prq;  args.x[1] = prk;  args.x[2] = prv;
    args.W[0] = prwq; args.W[1] = prwk; args.W[2] = prwv;
    args.b[0] = bq;   args.b[1] = bk;   args.b[2] = bv;
    args.out[0] = pQ; args.out[1] = pK; args.out[2] = pV;

    qkv_gemm_kernel<<<dim3(DMODEL / TBN, MROWS / TBM, 3), 256, GEMM_SMEM>>>(args);

    flash_mma_kernel<<<dim3(SEQ / FQ, BATCH * NHEAD), 256, FLASH_SMEM>>>(pQ, pK, pV, pA);

    o_gemm_kernel<<<dim3(DMODEL / TBN, MROWS / TBM), 256, GEMM_SMEM>>>(pA, prwo, bo, out);
}